// round 14
// baseline (speedup 1.0000x reference)
#include <cuda_runtime.h>

// ---------------------------------------------------------------------------
// ARAP forward — batch-interleaved gather layout, B=4 specialized.
// R14: packed f32x2 moment accumulation (fma/add/mul.rn.f32x2 via inline PTX;
//      SASS FFMA2 — ptxas never emits it from C++). Per-edge FP instr 36->18.
//      d computed as p + (-c): products bitwise-identical to the scalar form.
// Kept: R11 Eberly eigensolver, 64-reg point, metadata preload, 128-thr
// blocks, smem-staged coalesced outputs, single-pass algebraic energies.
// ---------------------------------------------------------------------------

#define MAXV (4 * 65536)

__device__ float4 g_pack2[2 * MAXV];   // index 2*(j*4+b) rest, +1 deformed

// ---- f32x2 packed helpers (inline PTX; sm_103a dual-lane FP32) ------------
#define F2PACK(out, lo, hi) \
    asm("mov.b64 %0, {%1, %2};" : "=l"(out) : "f"(lo), "f"(hi))
#define F2UNPACK(lo, hi, in) \
    asm("mov.b64 {%0, %1}, %2;" : "=f"(lo), "=f"(hi) : "l"(in))
#define F2ADD(out, a, bb_) \
    asm("add.rn.f32x2 %0, %1, %2;" : "=l"(out) : "l"(a), "l"(bb_))
#define F2MUL(out, a, bb_) \
    asm("mul.rn.f32x2 %0, %1, %2;" : "=l"(out) : "l"(a), "l"(bb_))
#define F2FMA(acc, a, bb_) \
    asm("fma.rn.f32x2 %0, %1, %2, %0;" : "+l"(acc) : "l"(a), "l"(bb_))

// B==4 pack: 128 vertices x 4 batches per 512-thread block, smem-staged.
__global__ void __launch_bounds__(512)
pack4_smem(const float* __restrict__ x1, const float* __restrict__ x2, int N) {
    __shared__ float s1[4 * 385];
    __shared__ float s2[4 * 385];
    int j0  = blockIdx.x * 128;
    int tid = threadIdx.x;

    for (int idx = tid; idx < 1536; idx += 512) {
        int b = idx / 384, k = idx - b * 384;
        s1[b * 385 + k] = x1[((size_t)b * N + j0) * 3 + k];
        s2[b * 385 + k] = x2[((size_t)b * N + j0) * 3 + k];
    }
    __syncthreads();

    int v = tid >> 2, b = tid & 3;
    int j = j0 + v;
    int si = b * 385 + v * 3;
    int t = j * 4 + b;
    g_pack2[2 * t]     = make_float4(s1[si], s1[si + 1], s1[si + 2], 0.f);
    g_pack2[2 * t + 1] = make_float4(s2[si], s2[si + 1], s2[si + 2], 0.f);
}

// Generic fallback pack (any B).
__global__ void pack_naive(const float* __restrict__ x1,
                           const float* __restrict__ x2,
                           int B, int N) {
    int t = blockIdx.x * blockDim.x + threadIdx.x;
    if (t >= B * N) return;
    int i = t / B, b = t - i * B;
    const float* p1 = x1 + ((size_t)b * N + i) * 3;
    const float* p2 = x2 + ((size_t)b * N + i) * 3;
    g_pack2[2 * t]     = make_float4(p1[0], p1[1], p1[2], 0.f);
    g_pack2[2 * t + 1] = make_float4(p2[0], p2[1], p2[2], 0.f);
}

__device__ __forceinline__ float3 cross3(float ax, float ay, float az,
                                         float bx, float by, float bz) {
    return make_float3(ay * bz - az * by,
                       az * bx - ax * bz,
                       ax * by - ay * bx);
}

// Unit eigenvector of symmetric A for eigenvalue lam: max-norm cross product
// of rows of (A - lam I). Select-based, no branches.
__device__ __forceinline__ float3 eigvec(const float A[3][3], float lam) {
    float r0x = A[0][0] - lam, r0y = A[0][1],       r0z = A[0][2];
    float r1x = A[1][0],       r1y = A[1][1] - lam, r1z = A[1][2];
    float r2x = A[2][0],       r2y = A[2][1],       r2z = A[2][2] - lam;
    float3 c0 = cross3(r0x, r0y, r0z, r1x, r1y, r1z);
    float3 c1 = cross3(r0x, r0y, r0z, r2x, r2y, r2z);
    float3 c2 = cross3(r1x, r1y, r1z, r2x, r2y, r2z);
    float n0 = c0.x*c0.x + c0.y*c0.y + c0.z*c0.z;
    float n1 = c1.x*c1.x + c1.y*c1.y + c1.z*c1.z;
    float n2 = c2.x*c2.x + c2.y*c2.y + c2.z*c2.z;

    float3 best = c0; float nb = n0;
    best = (n1 > nb) ? c1 : best; nb = (n1 > nb) ? n1 : nb;
    best = (n2 > nb) ? c2 : best; nb = (n2 > nb) ? n2 : nb;
    bool bad = nb < 1e-28f;
    best.x = bad ? 1.f : best.x;
    best.y = bad ? 0.f : best.y;
    best.z = bad ? 0.f : best.z;
    nb     = bad ? 1.f : nb;
    float inv = rsqrtf(nb);
    return make_float3(best.x * inv, best.y * inv, best.z * inv);
}

// Computes R (row-major in Rr[9]) and energies e[3] from the moments.
// R11 Eberly path: closed-form lam0, cross-product v0, exact complement 2x2.
__device__ __forceinline__ void solve_cell(
    float S00, float S01, float S02, float S10, float S11, float S12,
    float S20, float S21, float S22,
    float p00, float p01, float p02, float p11, float p12, float p22,
    float q0, float q1, float q2,
    float* __restrict__ Rr, float* __restrict__ e)
{
    float S[3][3] = {{S00,S01,S02},{S10,S11,S12},{S20,S21,S22}};
    float A[3][3];
    #pragma unroll
    for (int p = 0; p < 3; p++)
        #pragma unroll
        for (int q = 0; q < 3; q++)
            A[p][q] = S[0][p] * S[0][q] + S[1][p] * S[1][q] + S[2][p] * S[2][q];

    float m   = (A[0][0] + A[1][1] + A[2][2]) * (1.f / 3.f);
    float k00 = A[0][0] - m, k11 = A[1][1] - m, k22 = A[2][2] - m;
    float off = A[0][1]*A[0][1] + A[0][2]*A[0][2] + A[1][2]*A[1][2];
    float p2  = k00*k00 + k11*k11 + k22*k22 + 2.f * off;
    float p   = sqrtf(p2 * (1.f / 6.f));
    float pinv = __fdividef(1.f, fmaxf(p, 1e-20f));
    float b00 = k00 * pinv, b11 = k11 * pinv, b22 = k22 * pinv;
    float b01 = A[0][1] * pinv, b02 = A[0][2] * pinv, b12 = A[1][2] * pinv;
    float detB = b00 * (b11 * b22 - b12 * b12)
               - b01 * (b01 * b22 - b12 * b02)
               + b02 * (b01 * b12 - b11 * b02);
    float rr  = fminf(fmaxf(0.5f * detB, -1.f), 1.f);
    float phi = acosf(rr) * (1.f / 3.f);
    float lam0 = m + 2.f * p * __cosf(phi);

    float3 v0 = eigvec(A, lam0);

    float axv = fabsf(v0.x), ayv = fabsf(v0.y), azv = fabsf(v0.z);
    bool px = (axv <= ayv) && (axv <= azv);
    bool py = (!px) && (ayv <= azv);
    float Ux = px ? 0.f    : (py ? -v0.z : v0.y);
    float Uy = px ? v0.z   : (py ? 0.f   : -v0.x);
    float Uz = px ? -v0.y  : (py ? v0.x  : 0.f);
    float nu = rsqrtf(fmaxf(Ux*Ux + Uy*Uy + Uz*Uz, 1e-30f));
    Ux *= nu; Uy *= nu; Uz *= nu;
    float Wx = v0.y*Uz - v0.z*Uy;
    float Wy = v0.z*Ux - v0.x*Uz;
    float Wz = v0.x*Uy - v0.y*Ux;

    float AUx = A[0][0]*Ux + A[0][1]*Uy + A[0][2]*Uz;
    float AUy = A[1][0]*Ux + A[1][1]*Uy + A[1][2]*Uz;
    float AUz = A[2][0]*Ux + A[2][1]*Uy + A[2][2]*Uz;
    float AWx = A[0][0]*Wx + A[0][1]*Wy + A[0][2]*Wz;
    float AWy = A[1][0]*Wx + A[1][1]*Wy + A[1][2]*Wz;
    float AWz = A[2][0]*Wx + A[2][1]*Wy + A[2][2]*Wz;
    float aa = Ux*AUx + Uy*AUy + Uz*AUz;
    float bb = Ux*AWx + Uy*AWy + Uz*AWz;
    float cc = Wx*AWx + Wy*AWy + Wz*AWz;

    float half = 0.5f * (aa + cc);
    float diff = 0.5f * (aa - cc);
    float rad  = sqrtf(diff*diff + bb*bb);
    float mu1  = half + rad;
    float c1x = bb,       c1y = mu1 - aa;
    float c2x = mu1 - cc, c2y = bb;
    float n1c = c1x*c1x + c1y*c1y;
    float n2c = c2x*c2x + c2y*c2y;
    float exv = (n2c > n1c) ? c2x : c1x;
    float eyv = (n2c > n1c) ? c2y : c1y;
    float nn  = fmaxf(n1c, n2c);
    bool deg  = nn < 1e-28f;
    float ninv = deg ? 1.f : rsqrtf(nn);
    float cs = deg ? 1.f : exv * ninv;
    float sn = deg ? 0.f : eyv * ninv;

    float v1x = cs*Ux + sn*Wx, v1y = cs*Uy + sn*Wy, v1z = cs*Uz + sn*Wz;
    float v2x = cs*Wx - sn*Ux, v2y = cs*Wy - sn*Uy, v2z = cs*Wz - sn*Uz;
    float v0x = v0.x, v0y = v0.y, v0z = v0.z;

    float u0x = S[0][0]*v0x + S[0][1]*v0y + S[0][2]*v0z;
    float u0y = S[1][0]*v0x + S[1][1]*v0y + S[1][2]*v0z;
    float u0z = S[2][0]*v0x + S[2][1]*v0y + S[2][2]*v0z;
    float u1x = S[0][0]*v1x + S[0][1]*v1y + S[0][2]*v1z;
    float u1y = S[1][0]*v1x + S[1][1]*v1y + S[1][2]*v1z;
    float u1z = S[2][0]*v1x + S[2][1]*v1y + S[2][2]*v1z;
    float u2x = S[0][0]*v2x + S[0][1]*v2y + S[0][2]*v2z;
    float u2y = S[1][0]*v2x + S[1][1]*v2y + S[1][2]*v2z;
    float u2z = S[2][0]*v2x + S[2][1]*v2y + S[2][2]*v2z;

    float n0 = rsqrtf(fmaxf(u0x*u0x + u0y*u0y + u0z*u0z, 1e-30f));
    float n1 = rsqrtf(fmaxf(u1x*u1x + u1y*u1y + u1z*u1z, 1e-30f));
    float n2 = rsqrtf(fmaxf(u2x*u2x + u2y*u2y + u2z*u2z, 1e-30f));
    u0x*=n0; u0y*=n0; u0z*=n0;
    u1x*=n1; u1y*=n1; u1z*=n1;
    u2x*=n2; u2y*=n2; u2z*=n2;

    float detS = S[0][0]*(S[1][1]*S[2][2] - S[1][2]*S[2][1])
               - S[0][1]*(S[1][0]*S[2][2] - S[1][2]*S[2][0])
               + S[0][2]*(S[1][0]*S[2][1] - S[1][1]*S[2][0]);
    float sgn = (detS < 0.f) ? -1.f : 1.f;
    u2x *= sgn; u2y *= sgn; u2z *= sgn;

    float R00 = v0x*u0x + v1x*u1x + v2x*u2x;
    float R01 = v0x*u0y + v1x*u1y + v2x*u2y;
    float R02 = v0x*u0z + v1x*u1z + v2x*u2z;
    float R10 = v0y*u0x + v1y*u1x + v2y*u2x;
    float R11 = v0y*u0y + v1y*u1y + v2y*u2y;
    float R12 = v0y*u0z + v1y*u1z + v2y*u2z;
    float R20 = v0z*u0x + v1z*u1x + v2z*u2x;
    float R21 = v0z*u0y + v1z*u1y + v2z*u2y;
    float R22 = v0z*u0z + v1z*u1z + v2z*u2z;

    e[0] = fmaxf(q0
        - 2.f * (R00*S00 + R01*S10 + R02*S20)
        + R00*R00*p00 + R01*R01*p11 + R02*R02*p22
        + 2.f * (R00*R01*p01 + R00*R02*p02 + R01*R02*p12), 0.f);
    e[1] = fmaxf(q1
        - 2.f * (R10*S01 + R11*S11 + R12*S21)
        + R10*R10*p00 + R11*R11*p11 + R12*R12*p22
        + 2.f * (R10*R11*p01 + R10*R12*p02 + R11*R12*p12), 0.f);
    e[2] = fmaxf(q2
        - 2.f * (R20*S02 + R21*S12 + R22*S22)
        + R20*R20*p00 + R21*R21*p11 + R22*R22*p22
        + 2.f * (R20*R21*p01 + R20*R22*p02 + R21*R22*p12), 0.f);

    Rr[0]=R00; Rr[1]=R01; Rr[2]=R02;
    Rr[3]=R10; Rr[4]=R11; Rr[5]=R12;
    Rr[6]=R20; Rr[7]=R21; Rr[8]=R22;
}

// Packed-f32x2 per-edge accumulation. Accumulator pairing:
//   aS00S10=(S00,S10) aS01S11=(S01,S11) aS02S12=(S02,S12) aS20S21=(S20,S21)
//   aS22p22=(S22,p22) ap00p11=(p00,p11) ap01p12=(p01,p12) aq0q1=(q0,q1)
//   p02, q2 scalar.
// d = p + (-c): products (-a)(-b)=ab are bitwise-identical to scalar d=c-p.
#define EDGE_ACC2(j_, w_)                                                    \
    {                                                                        \
        const ulonglong2* pp = (const ulonglong2*)&g_pack2[2 * ((j_) * 4 + b)]; \
        ulonglong2 P1 = pp[0], P2 = pp[1];                                   \
        unsigned long long D1A, D1B, D2A, D2B, WW, WXY, VXY;                 \
        F2ADD(D1A, P1.x, NC1A);  /* (d1x,d1y) */                             \
        F2ADD(D1B, P1.y, NC1B);  /* (d1z, 0 ) */                             \
        F2ADD(D2A, P2.x, NC2A);  /* (d2x,d2y) */                             \
        F2ADD(D2B, P2.y, NC2B);  /* (d2z, 0 ) */                             \
        F2PACK(WW, (w_), (w_));                                              \
        F2MUL(WXY, WW, D1A);     /* (wx,wy)  */                              \
        F2MUL(VXY, WW, D2A);     /* (vx,vy)  */                              \
        float d1y_, d1z_, d2z_, wx_, wy_, jj_;                               \
        F2UNPACK(jj_,  d1y_, D1A);                                           \
        F2UNPACK(d1z_, jj_,  D1B);                                           \
        F2UNPACK(d2z_, jj_,  D2B);                                           \
        F2UNPACK(wx_,  wy_,  WXY);                                           \
        float wz_ = (w_) * d1z_;                                             \
        float vz_ = (w_) * d2z_;                                             \
        unsigned long long D2XX, D2YY, D2ZZ, WZZ, D1YZ, DZ21;                \
        float d2x_, d2y_;                                                    \
        F2UNPACK(d2x_, d2y_, D2A);                                           \
        F2PACK(D2XX, d2x_, d2x_);                                            \
        F2PACK(D2YY, d2y_, d2y_);                                            \
        F2PACK(D2ZZ, d2z_, d2z_);                                            \
        F2PACK(WZZ,  wz_,  wz_);                                             \
        F2PACK(D1YZ, d1y_, d1z_);                                            \
        F2PACK(DZ21, d2z_, d1z_);                                            \
        F2FMA(aS00S10, WXY, D2XX);                                           \
        F2FMA(aS01S11, WXY, D2YY);                                           \
        F2FMA(aS02S12, WXY, D2ZZ);                                           \
        F2FMA(aS20S21, WZZ, D2A);                                            \
        F2FMA(aS22p22, WZZ, DZ21);                                           \
        F2FMA(ap00p11, WXY, D1A);                                            \
        F2FMA(ap01p12, WXY, D1YZ);                                           \
        F2FMA(aq0q1,   VXY, D2A);                                            \
        p02 = fmaf(wx_, d1z_, p02);                                          \
        q2  = fmaf(vz_, d2z_, q2);                                           \
    }

// Specialized B==4, K==16, N%32==0 main kernel: 128-thread blocks,
// 32 vertices per block (grid exact; no tail). (128,8) => 64 regs, 32 warps/SM.
__global__ void __launch_bounds__(128, 8)
arap_main4(const int*   __restrict__ nbrList,
           const float* __restrict__ wMat,
           const float* __restrict__ arapW,
           float*       __restrict__ out,
           int N)
{
    __shared__ float se[4 * 100];   // energies: 32 v * 3 per batch (+pad)
    __shared__ float sr[4 * 292];   // rotations: 32 v * 9 per batch (+pad)

    int tid = threadIdx.x;
    int i0  = blockIdx.x * 32;
    int v   = tid >> 2;
    int b   = tid & 3;
    int i   = i0 + v;
    int t   = (i << 2) | b;
    int total = 4 * N;

    float4 c1 = g_pack2[2 * t];
    float4 c2 = g_pack2[2 * t + 1];
    int start = i << 4;             // accN[i] = 16*i (host-side guard)

    // Pre-negated packed centers for d = p + (-c).
    unsigned long long NC1A, NC1B, NC2A, NC2B;
    F2PACK(NC1A, -c1.x, -c1.y);
    F2PACK(NC1B, -c1.z, 0.f);
    F2PACK(NC2A, -c2.x, -c2.y);
    F2PACK(NC2B, -c2.z, 0.f);

    const int4*   nb4 = (const int4*)(nbrList + start);
    const float4* wv4 = (const float4*)(wMat + start);
    int4   nb0 = nb4[0], nb1 = nb4[1], nb2 = nb4[2], nb3 = nb4[3];
    float4 wv0 = wv4[0], wv1 = wv4[1], wv2 = wv4[2], wv3 = wv4[3];

    unsigned long long aS00S10 = 0ull, aS01S11 = 0ull, aS02S12 = 0ull,
                       aS20S21 = 0ull, aS22p22 = 0ull, ap00p11 = 0ull,
                       ap01p12 = 0ull, aq0q1   = 0ull;
    float p02 = 0.f, q2 = 0.f;

    EDGE_ACC2(nb0.x, wv0.x) EDGE_ACC2(nb0.y, wv0.y)
    EDGE_ACC2(nb0.z, wv0.z) EDGE_ACC2(nb0.w, wv0.w)
    EDGE_ACC2(nb1.x, wv1.x) EDGE_ACC2(nb1.y, wv1.y)
    EDGE_ACC2(nb1.z, wv1.z) EDGE_ACC2(nb1.w, wv1.w)
    EDGE_ACC2(nb2.x, wv2.x) EDGE_ACC2(nb2.y, wv2.y)
    EDGE_ACC2(nb2.z, wv2.z) EDGE_ACC2(nb2.w, wv2.w)
    EDGE_ACC2(nb3.x, wv3.x) EDGE_ACC2(nb3.y, wv3.y)
    EDGE_ACC2(nb3.z, wv3.z) EDGE_ACC2(nb3.w, wv3.w)

    float S00, S10, S01, S11, S02, S12, S20, S21, S22;
    float p00, p11, p01, p12, p22, q0, q1;
    F2UNPACK(S00, S10, aS00S10);
    F2UNPACK(S01, S11, aS01S11);
    F2UNPACK(S02, S12, aS02S12);
    F2UNPACK(S20, S21, aS20S21);
    F2UNPACK(S22, p22, aS22p22);
    F2UNPACK(p00, p11, ap00p11);
    F2UNPACK(p01, p12, ap01p12);
    F2UNPACK(q0,  q1,  aq0q1);

    float Rr[9], e[3];
    solve_cell(S00,S01,S02,S10,S11,S12,S20,S21,S22,
               p00,p01,p02,p11,p12,p22,q0,q1,q2, Rr, e);

    float aw = arapW[0];
    se[b * 100 + v * 3 + 0] = aw * e[0];
    se[b * 100 + v * 3 + 1] = aw * e[1];
    se[b * 100 + v * 3 + 2] = aw * e[2];
    #pragma unroll
    for (int k = 0; k < 9; k++) sr[b * 292 + v * 9 + k] = Rr[k];

    __syncthreads();

    // Energies: 4 segments x 24 float4 = 96 copies, fully coalesced.
    if (tid < 96) {
        int bb = tid / 24, k = tid - bb * 24;
        float4* dst = (float4*)(out + ((size_t)bb * N + i0) * 3);
        dst[k] = ((const float4*)(se + bb * 100))[k];
    }
    // Rotations: 4 segments x 72 float4 = 288 copies.
    #pragma unroll
    for (int idx = tid; idx < 288; idx += 128) {
        int bb = idx / 72, k = idx - bb * 72;
        float4* dst = (float4*)(out + (size_t)total * 3 + ((size_t)bb * N + i0) * 9);
        dst[k] = ((const float4*)(sr + bb * 292))[k];
    }
}

// Generic fallback (any B / ragged CSR), scalar accumulation, direct stores.
#define EDGE_ACC(Bv, j_, w_)                                                 \
    {                                                                        \
        const float4* pp = &g_pack2[2 * ((j_) * (Bv) + b)];                  \
        float4 p1v = pp[0], p2v = pp[1];                                     \
        float d1x = c1.x - p1v.x, d1y = c1.y - p1v.y, d1z = c1.z - p1v.z;    \
        float d2x = c2.x - p2v.x, d2y = c2.y - p2v.y, d2z = c2.z - p2v.z;    \
        float wx = (w_) * d1x, wy = (w_) * d1y, wz = (w_) * d1z;             \
        S00 += wx * d2x; S01 += wx * d2y; S02 += wx * d2z;                   \
        S10 += wy * d2x; S11 += wy * d2y; S12 += wy * d2z;                   \
        S20 += wz * d2x; S21 += wz * d2y; S22 += wz * d2z;                   \
        p00 += wx * d1x; p01 += wx * d1y; p02 += wx * d1z;                   \
        p11 += wy * d1y; p12 += wy * d1z; p22 += wz * d1z;                   \
        float vx = (w_) * d2x, vy = (w_) * d2y, vz = (w_) * d2z;             \
        q0 += vx * d2x; q1 += vy * d2y; q2 += vz * d2z;                      \
    }

__global__ void __launch_bounds__(256)
arap_main_gen(const int*   __restrict__ nbrList,
              const int*   __restrict__ numN,
              const int*   __restrict__ accN,
              const float* __restrict__ wMat,
              const float* __restrict__ arapW,
              float*       __restrict__ out,
              int B, int N)
{
    int t = blockIdx.x * blockDim.x + threadIdx.x;
    int total = B * N;
    if (t >= total) return;
    int i = t / B;
    int b = t - i * B;

    float4 c1 = g_pack2[2 * t];
    float4 c2 = g_pack2[2 * t + 1];
    int start = accN[i];
    int cnt   = numN[i];

    float S00=0.f,S01=0.f,S02=0.f,S10=0.f,S11=0.f,S12=0.f,S20=0.f,S21=0.f,S22=0.f;
    float p00=0.f,p01=0.f,p02=0.f,p11=0.f,p12=0.f,p22=0.f;
    float q0=0.f,q1=0.f,q2=0.f;

    for (int k = 0; k < cnt; k++) {
        int   j = nbrList[start + k];
        float w = wMat[start + k];
        EDGE_ACC(B, j, w)
    }

    float Rr[9], e[3];
    solve_cell(S00,S01,S02,S10,S11,S12,S20,S21,S22,
               p00,p01,p02,p11,p12,p22,q0,q1,q2, Rr, e);

    float aw = arapW[0];
    int told = b * N + i;
    size_t eo = (size_t)told * 3;
    out[eo + 0] = aw * e[0];
    out[eo + 1] = aw * e[1];
    out[eo + 2] = aw * e[2];
    size_t ro = (size_t)total * 3 + (size_t)told * 9;
    #pragma unroll
    for (int k = 0; k < 9; k++) out[ro + k] = Rr[k];
}

extern "C" void kernel_launch(void* const* d_in, const int* in_sizes, int n_in,
                              void* d_out, int out_size) {
    const float* xyz1 = (const float*)d_in[0];
    const float* xyz2 = (const float*)d_in[1];
    const int*   nbr  = (const int*)d_in[2];
    const int*   numN = (const int*)d_in[3];
    const int*   accN = (const int*)d_in[4];
    const float* wM   = (const float*)d_in[5];
    const float* aw   = (const float*)d_in[6];

    int N = in_sizes[3];                 // numNeighbors has N entries
    int B = in_sizes[0] / (3 * N);       // xyz1 is B*N*3
    int E = in_sizes[2];                 // neighborList length
    int total = B * N;

    bool fast = (B == 4) && ((N & 127) == 0) && (E == 16 * N);

    if (fast) {
        pack4_smem<<<N / 128, 512>>>(xyz1, xyz2, N);
        arap_main4<<<total / 128, 128>>>(nbr, wM, aw, (float*)d_out, N);
    } else {
        int threads = 256;
        int blocks = (total + threads - 1) / threads;
        pack_naive<<<blocks, threads>>>(xyz1, xyz2, B, N);
        arap_main_gen<<<blocks, threads>>>(nbr, numN, accN, wM, aw,
                                           (float*)d_out, B, N);
    }
}

// round 15
// speedup vs baseline: 1.0233x; 1.0233x over previous
#include <cuda_runtime.h>

// ---------------------------------------------------------------------------
// ARAP forward — batch-interleaved gather layout, B=4 specialized.
// R15: edge metadata staged through shared memory (conflict-free s[k*33+v]
//      layout, coalesced fill) instead of 32 pinned registers — frees ~30
//      regs inside the 64-reg/8-block envelope so ptxas can batch more
//      gather LDG.128s in flight (kernel is latency-bound at issue=43%).
// Kept: f32x2 packed accumulation, R11 Eberly eigensolver, (128,8) point,
// smem-staged coalesced outputs, single-pass algebraic energies.
// ---------------------------------------------------------------------------

#define MAXV (4 * 65536)

__device__ float4 g_pack2[2 * MAXV];   // index 2*(j*4+b) rest, +1 deformed

// ---- f32x2 packed helpers (inline PTX; sm_103a dual-lane FP32) ------------
#define F2PACK(out, lo, hi) \
    asm("mov.b64 %0, {%1, %2};" : "=l"(out) : "f"(lo), "f"(hi))
#define F2UNPACK(lo, hi, in) \
    asm("mov.b64 {%0, %1}, %2;" : "=f"(lo), "=f"(hi) : "l"(in))
#define F2ADD(out, a, bb_) \
    asm("add.rn.f32x2 %0, %1, %2;" : "=l"(out) : "l"(a), "l"(bb_))
#define F2MUL(out, a, bb_) \
    asm("mul.rn.f32x2 %0, %1, %2;" : "=l"(out) : "l"(a), "l"(bb_))
#define F2FMA(acc, a, bb_) \
    asm("fma.rn.f32x2 %0, %1, %2, %0;" : "+l"(acc) : "l"(a), "l"(bb_))

// B==4 pack: 128 vertices x 4 batches per 512-thread block, smem-staged.
__global__ void __launch_bounds__(512)
pack4_smem(const float* __restrict__ x1, const float* __restrict__ x2, int N) {
    __shared__ float s1[4 * 385];
    __shared__ float s2[4 * 385];
    int j0  = blockIdx.x * 128;
    int tid = threadIdx.x;

    for (int idx = tid; idx < 1536; idx += 512) {
        int b = idx / 384, k = idx - b * 384;
        s1[b * 385 + k] = x1[((size_t)b * N + j0) * 3 + k];
        s2[b * 385 + k] = x2[((size_t)b * N + j0) * 3 + k];
    }
    __syncthreads();

    int v = tid >> 2, b = tid & 3;
    int j = j0 + v;
    int si = b * 385 + v * 3;
    int t = j * 4 + b;
    g_pack2[2 * t]     = make_float4(s1[si], s1[si + 1], s1[si + 2], 0.f);
    g_pack2[2 * t + 1] = make_float4(s2[si], s2[si + 1], s2[si + 2], 0.f);
}

// Generic fallback pack (any B).
__global__ void pack_naive(const float* __restrict__ x1,
                           const float* __restrict__ x2,
                           int B, int N) {
    int t = blockIdx.x * blockDim.x + threadIdx.x;
    if (t >= B * N) return;
    int i = t / B, b = t - i * B;
    const float* p1 = x1 + ((size_t)b * N + i) * 3;
    const float* p2 = x2 + ((size_t)b * N + i) * 3;
    g_pack2[2 * t]     = make_float4(p1[0], p1[1], p1[2], 0.f);
    g_pack2[2 * t + 1] = make_float4(p2[0], p2[1], p2[2], 0.f);
}

__device__ __forceinline__ float3 cross3(float ax, float ay, float az,
                                         float bx, float by, float bz) {
    return make_float3(ay * bz - az * by,
                       az * bx - ax * bz,
                       ax * by - ay * bx);
}

// Unit eigenvector of symmetric A for eigenvalue lam: max-norm cross product
// of rows of (A - lam I). Select-based, no branches.
__device__ __forceinline__ float3 eigvec(const float A[3][3], float lam) {
    float r0x = A[0][0] - lam, r0y = A[0][1],       r0z = A[0][2];
    float r1x = A[1][0],       r1y = A[1][1] - lam, r1z = A[1][2];
    float r2x = A[2][0],       r2y = A[2][1],       r2z = A[2][2] - lam;
    float3 c0 = cross3(r0x, r0y, r0z, r1x, r1y, r1z);
    float3 c1 = cross3(r0x, r0y, r0z, r2x, r2y, r2z);
    float3 c2 = cross3(r1x, r1y, r1z, r2x, r2y, r2z);
    float n0 = c0.x*c0.x + c0.y*c0.y + c0.z*c0.z;
    float n1 = c1.x*c1.x + c1.y*c1.y + c1.z*c1.z;
    float n2 = c2.x*c2.x + c2.y*c2.y + c2.z*c2.z;

    float3 best = c0; float nb = n0;
    best = (n1 > nb) ? c1 : best; nb = (n1 > nb) ? n1 : nb;
    best = (n2 > nb) ? c2 : best; nb = (n2 > nb) ? n2 : nb;
    bool bad = nb < 1e-28f;
    best.x = bad ? 1.f : best.x;
    best.y = bad ? 0.f : best.y;
    best.z = bad ? 0.f : best.z;
    nb     = bad ? 1.f : nb;
    float inv = rsqrtf(nb);
    return make_float3(best.x * inv, best.y * inv, best.z * inv);
}

// Computes R (row-major in Rr[9]) and energies e[3] from the moments.
// R11 Eberly path: closed-form lam0, cross-product v0, exact complement 2x2.
__device__ __forceinline__ void solve_cell(
    float S00, float S01, float S02, float S10, float S11, float S12,
    float S20, float S21, float S22,
    float p00, float p01, float p02, float p11, float p12, float p22,
    float q0, float q1, float q2,
    float* __restrict__ Rr, float* __restrict__ e)
{
    float S[3][3] = {{S00,S01,S02},{S10,S11,S12},{S20,S21,S22}};
    float A[3][3];
    #pragma unroll
    for (int p = 0; p < 3; p++)
        #pragma unroll
        for (int q = 0; q < 3; q++)
            A[p][q] = S[0][p] * S[0][q] + S[1][p] * S[1][q] + S[2][p] * S[2][q];

    float m   = (A[0][0] + A[1][1] + A[2][2]) * (1.f / 3.f);
    float k00 = A[0][0] - m, k11 = A[1][1] - m, k22 = A[2][2] - m;
    float off = A[0][1]*A[0][1] + A[0][2]*A[0][2] + A[1][2]*A[1][2];
    float p2  = k00*k00 + k11*k11 + k22*k22 + 2.f * off;
    float p   = sqrtf(p2 * (1.f / 6.f));
    float pinv = __fdividef(1.f, fmaxf(p, 1e-20f));
    float b00 = k00 * pinv, b11 = k11 * pinv, b22 = k22 * pinv;
    float b01 = A[0][1] * pinv, b02 = A[0][2] * pinv, b12 = A[1][2] * pinv;
    float detB = b00 * (b11 * b22 - b12 * b12)
               - b01 * (b01 * b22 - b12 * b02)
               + b02 * (b01 * b12 - b11 * b02);
    float rr  = fminf(fmaxf(0.5f * detB, -1.f), 1.f);
    float phi = acosf(rr) * (1.f / 3.f);
    float lam0 = m + 2.f * p * __cosf(phi);

    float3 v0 = eigvec(A, lam0);

    float axv = fabsf(v0.x), ayv = fabsf(v0.y), azv = fabsf(v0.z);
    bool px = (axv <= ayv) && (axv <= azv);
    bool py = (!px) && (ayv <= azv);
    float Ux = px ? 0.f    : (py ? -v0.z : v0.y);
    float Uy = px ? v0.z   : (py ? 0.f   : -v0.x);
    float Uz = px ? -v0.y  : (py ? v0.x  : 0.f);
    float nu = rsqrtf(fmaxf(Ux*Ux + Uy*Uy + Uz*Uz, 1e-30f));
    Ux *= nu; Uy *= nu; Uz *= nu;
    float Wx = v0.y*Uz - v0.z*Uy;
    float Wy = v0.z*Ux - v0.x*Uz;
    float Wz = v0.x*Uy - v0.y*Ux;

    float AUx = A[0][0]*Ux + A[0][1]*Uy + A[0][2]*Uz;
    float AUy = A[1][0]*Ux + A[1][1]*Uy + A[1][2]*Uz;
    float AUz = A[2][0]*Ux + A[2][1]*Uy + A[2][2]*Uz;
    float AWx = A[0][0]*Wx + A[0][1]*Wy + A[0][2]*Wz;
    float AWy = A[1][0]*Wx + A[1][1]*Wy + A[1][2]*Wz;
    float AWz = A[2][0]*Wx + A[2][1]*Wy + A[2][2]*Wz;
    float aa = Ux*AUx + Uy*AUy + Uz*AUz;
    float bb = Ux*AWx + Uy*AWy + Uz*AWz;
    float cc = Wx*AWx + Wy*AWy + Wz*AWz;

    float half = 0.5f * (aa + cc);
    float diff = 0.5f * (aa - cc);
    float rad  = sqrtf(diff*diff + bb*bb);
    float mu1  = half + rad;
    float c1x = bb,       c1y = mu1 - aa;
    float c2x = mu1 - cc, c2y = bb;
    float n1c = c1x*c1x + c1y*c1y;
    float n2c = c2x*c2x + c2y*c2y;
    float exv = (n2c > n1c) ? c2x : c1x;
    float eyv = (n2c > n1c) ? c2y : c1y;
    float nn  = fmaxf(n1c, n2c);
    bool deg  = nn < 1e-28f;
    float ninv = deg ? 1.f : rsqrtf(nn);
    float cs = deg ? 1.f : exv * ninv;
    float sn = deg ? 0.f : eyv * ninv;

    float v1x = cs*Ux + sn*Wx, v1y = cs*Uy + sn*Wy, v1z = cs*Uz + sn*Wz;
    float v2x = cs*Wx - sn*Ux, v2y = cs*Wy - sn*Uy, v2z = cs*Wz - sn*Uz;
    float v0x = v0.x, v0y = v0.y, v0z = v0.z;

    float u0x = S[0][0]*v0x + S[0][1]*v0y + S[0][2]*v0z;
    float u0y = S[1][0]*v0x + S[1][1]*v0y + S[1][2]*v0z;
    float u0z = S[2][0]*v0x + S[2][1]*v0y + S[2][2]*v0z;
    float u1x = S[0][0]*v1x + S[0][1]*v1y + S[0][2]*v1z;
    float u1y = S[1][0]*v1x + S[1][1]*v1y + S[1][2]*v1z;
    float u1z = S[2][0]*v1x + S[2][1]*v1y + S[2][2]*v1z;
    float u2x = S[0][0]*v2x + S[0][1]*v2y + S[0][2]*v2z;
    float u2y = S[1][0]*v2x + S[1][1]*v2y + S[1][2]*v2z;
    float u2z = S[2][0]*v2x + S[2][1]*v2y + S[2][2]*v2z;

    float n0 = rsqrtf(fmaxf(u0x*u0x + u0y*u0y + u0z*u0z, 1e-30f));
    float n1 = rsqrtf(fmaxf(u1x*u1x + u1y*u1y + u1z*u1z, 1e-30f));
    float n2 = rsqrtf(fmaxf(u2x*u2x + u2y*u2y + u2z*u2z, 1e-30f));
    u0x*=n0; u0y*=n0; u0z*=n0;
    u1x*=n1; u1y*=n1; u1z*=n1;
    u2x*=n2; u2y*=n2; u2z*=n2;

    float detS = S[0][0]*(S[1][1]*S[2][2] - S[1][2]*S[2][1])
               - S[0][1]*(S[1][0]*S[2][2] - S[1][2]*S[2][0])
               + S[0][2]*(S[1][0]*S[2][1] - S[1][1]*S[2][0]);
    float sgn = (detS < 0.f) ? -1.f : 1.f;
    u2x *= sgn; u2y *= sgn; u2z *= sgn;

    float R00 = v0x*u0x + v1x*u1x + v2x*u2x;
    float R01 = v0x*u0y + v1x*u1y + v2x*u2y;
    float R02 = v0x*u0z + v1x*u1z + v2x*u2z;
    float R10 = v0y*u0x + v1y*u1x + v2y*u2x;
    float R11 = v0y*u0y + v1y*u1y + v2y*u2y;
    float R12 = v0y*u0z + v1y*u1z + v2y*u2z;
    float R20 = v0z*u0x + v1z*u1x + v2z*u2x;
    float R21 = v0z*u0y + v1z*u1y + v2z*u2y;
    float R22 = v0z*u0z + v1z*u1z + v2z*u2z;

    e[0] = fmaxf(q0
        - 2.f * (R00*S00 + R01*S10 + R02*S20)
        + R00*R00*p00 + R01*R01*p11 + R02*R02*p22
        + 2.f * (R00*R01*p01 + R00*R02*p02 + R01*R02*p12), 0.f);
    e[1] = fmaxf(q1
        - 2.f * (R10*S01 + R11*S11 + R12*S21)
        + R10*R10*p00 + R11*R11*p11 + R12*R12*p22
        + 2.f * (R10*R11*p01 + R10*R12*p02 + R11*R12*p12), 0.f);
    e[2] = fmaxf(q2
        - 2.f * (R20*S02 + R21*S12 + R22*S22)
        + R20*R20*p00 + R21*R21*p11 + R22*R22*p22
        + 2.f * (R20*R21*p01 + R20*R22*p02 + R21*R22*p12), 0.f);

    Rr[0]=R00; Rr[1]=R01; Rr[2]=R02;
    Rr[3]=R10; Rr[4]=R11; Rr[5]=R12;
    Rr[6]=R20; Rr[7]=R21; Rr[8]=R22;
}

// Packed-f32x2 per-edge accumulation (see R14 notes). j_/w_ now come from
// shared memory (conflict-free layout), not pinned registers.
#define EDGE_ACC2(j_, w_)                                                    \
    {                                                                        \
        const ulonglong2* pp = (const ulonglong2*)&g_pack2[2 * ((j_) * 4 + b)]; \
        ulonglong2 P1 = pp[0], P2 = pp[1];                                   \
        unsigned long long D1A, D1B, D2A, D2B, WW, WXY, VXY;                 \
        F2ADD(D1A, P1.x, NC1A);  /* (d1x,d1y) */                             \
        F2ADD(D1B, P1.y, NC1B);  /* (d1z, 0 ) */                             \
        F2ADD(D2A, P2.x, NC2A);  /* (d2x,d2y) */                             \
        F2ADD(D2B, P2.y, NC2B);  /* (d2z, 0 ) */                             \
        F2PACK(WW, (w_), (w_));                                              \
        F2MUL(WXY, WW, D1A);     /* (wx,wy)  */                              \
        F2MUL(VXY, WW, D2A);     /* (vx,vy)  */                              \
        float d1y_, d1z_, d2z_, wx_, wy_, jj_;                               \
        F2UNPACK(jj_,  d1y_, D1A);                                           \
        F2UNPACK(d1z_, jj_,  D1B);                                           \
        F2UNPACK(d2z_, jj_,  D2B);                                           \
        F2UNPACK(wx_,  wy_,  WXY);                                           \
        float wz_ = (w_) * d1z_;                                             \
        float vz_ = (w_) * d2z_;                                             \
        unsigned long long D2XX, D2YY, D2ZZ, WZZ, D1YZ, DZ21;                \
        float d2x_, d2y_;                                                    \
        F2UNPACK(d2x_, d2y_, D2A);                                           \
        F2PACK(D2XX, d2x_, d2x_);                                            \
        F2PACK(D2YY, d2y_, d2y_);                                            \
        F2PACK(D2ZZ, d2z_, d2z_);                                            \
        F2PACK(WZZ,  wz_,  wz_);                                             \
        F2PACK(D1YZ, d1y_, d1z_);                                            \
        F2PACK(DZ21, d2z_, d1z_);                                            \
        F2FMA(aS00S10, WXY, D2XX);                                           \
        F2FMA(aS01S11, WXY, D2YY);                                           \
        F2FMA(aS02S12, WXY, D2ZZ);                                           \
        F2FMA(aS20S21, WZZ, D2A);                                            \
        F2FMA(aS22p22, WZZ, DZ21);                                           \
        F2FMA(ap00p11, WXY, D1A);                                            \
        F2FMA(ap01p12, WXY, D1YZ);                                           \
        F2FMA(aq0q1,   VXY, D2A);                                            \
        p02 = fmaf(wx_, d1z_, p02);                                          \
        q2  = fmaf(vz_, d2z_, q2);                                           \
    }

// Specialized B==4, K==16, N%32==0 main kernel: 128-thread blocks,
// 32 vertices per block. (128,8) => 64 regs, 32 warps/SM.
__global__ void __launch_bounds__(128, 8)
arap_main4(const int*   __restrict__ nbrList,
           const float* __restrict__ wMat,
           const float* __restrict__ arapW,
           float*       __restrict__ out,
           int N)
{
    // Edge metadata staging: s[k*33 + v] — per-warp reads hit 8 distinct
    // banks (v consecutive, quad-broadcast), compile-time k offsets.
    __shared__ int   snb[16 * 33];
    __shared__ float swv[16 * 33];
    __shared__ float se[4 * 100];   // energies: 32 v * 3 per batch (+pad)
    __shared__ float sr[4 * 292];   // rotations: 32 v * 9 per batch (+pad)

    int tid = threadIdx.x;
    int i0  = blockIdx.x * 32;
    int v   = tid >> 2;
    int b   = tid & 3;
    int i   = i0 + v;
    int t   = (i << 2) | b;
    int total = 4 * N;

    // Coalesced metadata fill: 512 ints each, 4 per thread.
    {
        const int*   gn = nbrList + (i0 << 4);
        const float* gw = wMat    + (i0 << 4);
        #pragma unroll
        for (int idx = tid; idx < 512; idx += 128) {
            int vv = idx >> 4, kk = idx & 15;
            snb[kk * 33 + vv] = gn[idx];
            swv[kk * 33 + vv] = gw[idx];
        }
    }

    float4 c1 = g_pack2[2 * t];
    float4 c2 = g_pack2[2 * t + 1];

    // Pre-negated packed centers for d = p + (-c).
    unsigned long long NC1A, NC1B, NC2A, NC2B;
    F2PACK(NC1A, -c1.x, -c1.y);
    F2PACK(NC1B, -c1.z, 0.f);
    F2PACK(NC2A, -c2.x, -c2.y);
    F2PACK(NC2B, -c2.z, 0.f);

    __syncthreads();

    unsigned long long aS00S10 = 0ull, aS01S11 = 0ull, aS02S12 = 0ull,
                       aS20S21 = 0ull, aS22p22 = 0ull, ap00p11 = 0ull,
                       ap01p12 = 0ull, aq0q1   = 0ull;
    float p02 = 0.f, q2 = 0.f;

    #pragma unroll
    for (int k = 0; k < 16; k++) {
        int   jn = snb[k * 33 + v];
        float wn = swv[k * 33 + v];
        EDGE_ACC2(jn, wn)
    }

    float S00, S10, S01, S11, S02, S12, S20, S21, S22;
    float p00, p11, p01, p12, p22, q0, q1;
    F2UNPACK(S00, S10, aS00S10);
    F2UNPACK(S01, S11, aS01S11);
    F2UNPACK(S02, S12, aS02S12);
    F2UNPACK(S20, S21, aS20S21);
    F2UNPACK(S22, p22, aS22p22);
    F2UNPACK(p00, p11, ap00p11);
    F2UNPACK(p01, p12, ap01p12);
    F2UNPACK(q0,  q1,  aq0q1);

    float Rr[9], e[3];
    solve_cell(S00,S01,S02,S10,S11,S12,S20,S21,S22,
               p00,p01,p02,p11,p12,p22,q0,q1,q2, Rr, e);

    float aw = arapW[0];
    se[b * 100 + v * 3 + 0] = aw * e[0];
    se[b * 100 + v * 3 + 1] = aw * e[1];
    se[b * 100 + v * 3 + 2] = aw * e[2];
    #pragma unroll
    for (int k = 0; k < 9; k++) sr[b * 292 + v * 9 + k] = Rr[k];

    __syncthreads();

    // Energies: 4 segments x 24 float4 = 96 copies, fully coalesced.
    if (tid < 96) {
        int bb = tid / 24, k = tid - bb * 24;
        float4* dst = (float4*)(out + ((size_t)bb * N + i0) * 3);
        dst[k] = ((const float4*)(se + bb * 100))[k];
    }
    // Rotations: 4 segments x 72 float4 = 288 copies.
    #pragma unroll
    for (int idx = tid; idx < 288; idx += 128) {
        int bb = idx / 72, k = idx - bb * 72;
        float4* dst = (float4*)(out + (size_t)total * 3 + ((size_t)bb * N + i0) * 9);
        dst[k] = ((const float4*)(sr + bb * 292))[k];
    }
}

// Generic fallback (any B / ragged CSR), scalar accumulation, direct stores.
#define EDGE_ACC(Bv, j_, w_)                                                 \
    {                                                                        \
        const float4* pp = &g_pack2[2 * ((j_) * (Bv) + b)];                  \
        float4 p1v = pp[0], p2v = pp[1];                                     \
        float d1x = c1.x - p1v.x, d1y = c1.y - p1v.y, d1z = c1.z - p1v.z;    \
        float d2x = c2.x - p2v.x, d2y = c2.y - p2v.y, d2z = c2.z - p2v.z;    \
        float wx = (w_) * d1x, wy = (w_) * d1y, wz = (w_) * d1z;             \
        S00 += wx * d2x; S01 += wx * d2y; S02 += wx * d2z;                   \
        S10 += wy * d2x; S11 += wy * d2y; S12 += wy * d2z;                   \
        S20 += wz * d2x; S21 += wz * d2y; S22 += wz * d2z;                   \
        p00 += wx * d1x; p01 += wx * d1y; p02 += wx * d1z;                   \
        p11 += wy * d1y; p12 += wy * d1z; p22 += wz * d1z;                   \
        float vx = (w_) * d2x, vy = (w_) * d2y, vz = (w_) * d2z;             \
        q0 += vx * d2x; q1 += vy * d2y; q2 += vz * d2z;                      \
    }

__global__ void __launch_bounds__(256)
arap_main_gen(const int*   __restrict__ nbrList,
              const int*   __restrict__ numN,
              const int*   __restrict__ accN,
              const float* __restrict__ wMat,
              const float* __restrict__ arapW,
              float*       __restrict__ out,
              int B, int N)
{
    int t = blockIdx.x * blockDim.x + threadIdx.x;
    int total = B * N;
    if (t >= total) return;
    int i = t / B;
    int b = t - i * B;

    float4 c1 = g_pack2[2 * t];
    float4 c2 = g_pack2[2 * t + 1];
    int start = accN[i];
    int cnt   = numN[i];

    float S00=0.f,S01=0.f,S02=0.f,S10=0.f,S11=0.f,S12=0.f,S20=0.f,S21=0.f,S22=0.f;
    float p00=0.f,p01=0.f,p02=0.f,p11=0.f,p12=0.f,p22=0.f;
    float q0=0.f,q1=0.f,q2=0.f;

    for (int k = 0; k < cnt; k++) {
        int   j = nbrList[start + k];
        float w = wMat[start + k];
        EDGE_ACC(B, j, w)
    }

    float Rr[9], e[3];
    solve_cell(S00,S01,S02,S10,S11,S12,S20,S21,S22,
               p00,p01,p02,p11,p12,p22,q0,q1,q2, Rr, e);

    float aw = arapW[0];
    int told = b * N + i;
    size_t eo = (size_t)told * 3;
    out[eo + 0] = aw * e[0];
    out[eo + 1] = aw * e[1];
    out[eo + 2] = aw * e[2];
    size_t ro = (size_t)total * 3 + (size_t)told * 9;
    #pragma unroll
    for (int k = 0; k < 9; k++) out[ro + k] = Rr[k];
}

extern "C" void kernel_launch(void* const* d_in, const int* in_sizes, int n_in,
                              void* d_out, int out_size) {
    const float* xyz1 = (const float*)d_in[0];
    const float* xyz2 = (const float*)d_in[1];
    const int*   nbr  = (const int*)d_in[2];
    const int*   numN = (const int*)d_in[3];
    const int*   accN = (const int*)d_in[4];
    const float* wM   = (const float*)d_in[5];
    const float* aw   = (const float*)d_in[6];

    int N = in_sizes[3];                 // numNeighbors has N entries
    int B = in_sizes[0] / (3 * N);       // xyz1 is B*N*3
    int E = in_sizes[2];                 // neighborList length
    int total = B * N;

    bool fast = (B == 4) && ((N & 127) == 0) && (E == 16 * N);

    if (fast) {
        pack4_smem<<<N / 128, 512>>>(xyz1, xyz2, N);
        arap_main4<<<total / 128, 128>>>(nbr, wM, aw, (float*)d_out, N);
    } else {
        int threads = 256;
        int blocks = (total + threads - 1) / threads;
        pack_naive<<<blocks, threads>>>(xyz1, xyz2, B, N);
        arap_main_gen<<<blocks, threads>>>(nbr, numN, accN, wM, aw,
                                           (float*)d_out, B, N);
    }
}